// round 13
// baseline (speedup 1.0000x reference)
#include <cuda_runtime.h>
#include <cstdint>
#include <cstdio>

#define HID 256
#define HS  512
#define NH  8
#define HD  64
#define NTOK 8
#define BB  8

__device__ float g_u[BB][NH][HID];
__device__ float g_s1[BB][HS];
__device__ float g_qh[BB][HS];
// Intermediate h, ed-major: g_h[ed][pix], pix = b*1024 + hrow*32 + w.  16.8 MB
__device__ float g_h[HS * 8192];

static __device__ __forceinline__ unsigned long long pk2(float lo, float hi){
  unsigned long long r; asm("mov.b64 %0, {%1,%2};" : "=l"(r) : "f"(lo), "f"(hi)); return r;
}
static __device__ __forceinline__ void upk2(unsigned long long v, float& lo, float& hi){
  asm("mov.b64 {%0,%1}, %2;" : "=f"(lo), "=f"(hi) : "l"(v));
}
static __device__ __forceinline__ unsigned long long f2fma(unsigned long long a, unsigned long long b, unsigned long long c){
  unsigned long long d; asm("fma.rn.f32x2 %0, %1, %2, %3;" : "=l"(d) : "l"(a), "l"(b), "l"(c)); return d;
}

// ---------------- setup stage 1: s1 = silu(emb[q] @ w1 + b1)   grid (8 b, 8 slice), 256 thr
__global__ void setup_s1(const int* __restrict__ q, const float* __restrict__ emb,
                         const float* __restrict__ w1, const float* __restrict__ b1)
{
  __shared__ float red[4][64];
  __shared__ float qe[HID];
  const int b = blockIdx.x, slice = blockIdx.y, t = threadIdx.x;
  if (t < HID) qe[t] = __ldg(emb + (size_t)__ldg(q + b)*HID + t);
  __syncthreads();
  const int cl = t & 63, qq = t >> 6;
  const int col = slice*64 + cl;
  const float* wcol = w1 + col;
  float a0=0.f, a1=0.f;
  const int i0 = qq*64;
  #pragma unroll 8
  for (int i=0; i<64; i+=2){
    a0 = fmaf(qe[i0+i  ], __ldg(wcol + (size_t)(i0+i  )*HS), a0);
    a1 = fmaf(qe[i0+i+1], __ldg(wcol + (size_t)(i0+i+1)*HS), a1);
  }
  red[qq][cl] = a0 + a1;
  __syncthreads();
  if (t < 64){
    float s = red[0][t]+red[1][t]+red[2][t]+red[3][t] + __ldg(b1 + slice*64 + t);
    g_s1[b][slice*64+t] = s / (1.f + expf(-s));
  }
}

// ---------------- setup stage 2: qh = s1 @ w2 + b2   grid (8 b, 8 slice), 256 thr
__global__ void setup_qh(const float* __restrict__ w2, const float* __restrict__ b2)
{
  __shared__ float red[4][64];
  __shared__ float s1s[HS];
  const int b = blockIdx.x, slice = blockIdx.y, t = threadIdx.x;
  s1s[t]     = g_s1[b][t];
  s1s[t+256] = g_s1[b][t+256];
  __syncthreads();
  const int cl = t & 63, qq = t >> 6;
  const int col = slice*64 + cl;
  const float* wcol = w2 + col;
  float a0=0.f, a1=0.f;
  const int i0 = qq*128;
  #pragma unroll 8
  for (int i=0; i<128; i+=2){
    a0 = fmaf(s1s[i0+i  ], __ldg(wcol + (size_t)(i0+i  )*HS), a0);
    a1 = fmaf(s1s[i0+i+1], __ldg(wcol + (size_t)(i0+i+1)*HS), a1);
  }
  red[qq][cl] = a0 + a1;
  __syncthreads();
  if (t < 64)
    g_qh[b][slice*64+t] = red[0][t]+red[1][t]+red[2][t]+red[3][t] + __ldg(b2 + slice*64 + t);
}

// ---------------- setup stage 3: u[b][e][ch] = (w_kv_k[ch,e,:] . qh[b,e,:]) * rms_w[ch]/8
__global__ void setup_u(const float* __restrict__ w_kv, const float* __restrict__ rms_w)
{
  __shared__ float qh_sm[64];
  const int b = blockIdx.x, e = blockIdx.y, t = threadIdx.x;
  if (t < 64) qh_sm[t] = g_qh[b][e*64 + t];
  __syncthreads();
  const float4* wk = reinterpret_cast<const float4*>(w_kv + (size_t)t*1024 + e*128);
  float a0=0.f, a1=0.f;
  #pragma unroll
  for (int j=0; j<16; j+=2){
    float4 v0 = __ldg(wk + j);
    float4 v1 = __ldg(wk + j + 1);
    a0 = fmaf(qh_sm[4*j+0], v0.x, a0);
    a0 = fmaf(qh_sm[4*j+1], v0.y, a0);
    a0 = fmaf(qh_sm[4*j+2], v0.z, a0);
    a0 = fmaf(qh_sm[4*j+3], v0.w, a0);
    a1 = fmaf(qh_sm[4*j+4], v1.x, a1);
    a1 = fmaf(qh_sm[4*j+5], v1.y, a1);
    a1 = fmaf(qh_sm[4*j+6], v1.z, a1);
    a1 = fmaf(qh_sm[4*j+7], v1.w, a1);
  }
  g_u[b][e][t] = (a0+a1) * __ldg(rms_w + t) * 0.125f;
}

// ---------------- kernel1 (R10, FROZEN): pass1 + softmax + g + h -> g_h (ed-major)
// smem (floats), 18944 total = 75.8KB -> 2 blocks/SM:
//  [0,256) rms | [256,512) rinv | [512,2560) attn | [2560,10752) cn (ur aliases) | [10752,18944) g
__global__ __launch_bounds__(256, 2) void main_kernel(const float* __restrict__ c,
    const float* __restrict__ rms_w, const float* __restrict__ w_kv)
{
  extern __shared__ float sm[];
  float* rms_sm  = sm;
  float* rinv_sm = sm + 256;
  float* attn_sm = sm + 512;
  float* cn_sm   = sm + 2560;
  float* ur_sm   = sm + 2560;   // alias (dead once chunk loop starts)
  float* g_sm    = sm + 10752;

  const int t  = threadIdx.x;
  const int bx = blockIdx.x;
  const int b  = bx >> 5, hrow = bx & 31;
  const int w  = t & 31;
  const int n  = t >> 5;        // warp id
  const int lane = w;

  rms_sm[t] = rms_w[t];
  {
    int ch = t;
    #pragma unroll
    for (int e=0;e<NH;e++) ur_sm[ch*NH + e] = g_u[b][e][ch];
  }
  __syncthreads();

  const float* cp = c + ((size_t)(b*NTOK + n)*HID)*1024 + hrow*32 + w;

  // ---- pass 1: stream c once (unroll-8 batched loads); rms sum + 8 head dots
  float ss = 0.f;
  unsigned long long s2[4];
  s2[0]=s2[1]=s2[2]=s2[3]=0ull;
  const unsigned long long* urp = reinterpret_cast<const unsigned long long*>(ur_sm);
  for (int c8=0; c8<32; c8++){
    float x[8];
    #pragma unroll
    for (int j=0;j<8;j++) x[j] = __ldg(cp + (size_t)(c8*8+j)*1024);
    #pragma unroll
    for (int j=0;j<8;j++){
      unsigned long long xd = pk2(x[j],x[j]);
      int ch = c8*8+j;
      ss = fmaf(x[j],x[j],ss);
      s2[0] = f2fma(xd, urp[ch*4+0], s2[0]);
      s2[1] = f2fma(xd, urp[ch*4+1], s2[1]);
      s2[2] = f2fma(xd, urp[ch*4+2], s2[2]);
      s2[3] = f2fma(xd, urp[ch*4+3], s2[3]);
    }
  }
  float rinv = rsqrtf(ss*(1.f/256.f) + 1e-6f);
  rinv_sm[n*32+w] = rinv;
  #pragma unroll
  for (int j=0;j<4;j++){
    float lo,hi; upk2(s2[j],lo,hi);
    attn_sm[(2*j  )*256 + n*32 + w] = lo*rinv;
    attn_sm[(2*j+1)*256 + n*32 + w] = hi*rinv;
  }
  __syncthreads();

  // ---- softmax over n: thread (e = n-slot, w)
  {
    int e = n;
    float d[8], m = -1e30f;
    #pragma unroll
    for (int i=0;i<8;i++){ d[i] = attn_sm[e*256 + i*32 + w]; m = fmaxf(m,d[i]); }
    float ssum = 0.f;
    #pragma unroll
    for (int i=0;i<8;i++){ d[i] = __expf(d[i]-m); ssum += d[i]; }
    float inv = 1.f/ssum;
    #pragma unroll
    for (int i=0;i<8;i++) attn_sm[e*256 + i*32 + w] = d[i]*inv;
  }
  __syncthreads();

  // ---- chunk loop: stage cn, compute g, accumulate h in registers
  const int e     = n;
  const int d0    = (lane & 7) * 8;
  const int wbase = lane >> 3;            // 0..3; w values wbase + 4k
  unsigned long long hacc[4][8];
  #pragma unroll
  for (int i=0;i<4;i++){
    #pragma unroll
    for (int k=0;k<8;k++) hacc[i][k]=0ull;
  }
  const ulonglong2* wvp_base =
      reinterpret_cast<const ulonglong2*>(w_kv + e*128 + 64 + d0);  // row stride 256 ull2

  for (int kc=0; kc<8; kc++){
    const int ch0 = kc*32;
    {
      #pragma unroll 4
      for (int cc=0; cc<32; cc++){
        float x = __ldg(cp + (size_t)(ch0+cc)*1024);
        cn_sm[n*1024 + cc*32 + w] = x * rinv * rms_sm[ch0+cc];
      }
    }
    __syncthreads();
    {
      int ccg = n;
      float ga[8][4];
      #pragma unroll
      for (int i=0;i<8;i++){
        #pragma unroll
        for (int j2=0;j2<4;j2++) ga[i][j2]=0.f;
      }
      #pragma unroll
      for (int nn=0; nn<8; nn++){
        float a[8];
        #pragma unroll
        for (int ee=0;ee<8;ee++) a[ee] = attn_sm[ee*256 + nn*32 + w];
        #pragma unroll
        for (int j2=0;j2<4;j2++){
          float cv = cn_sm[nn*1024 + (ccg*4+j2)*32 + w];
          #pragma unroll
          for (int ee=0;ee<8;ee++) ga[ee][j2] = fmaf(a[ee], cv, ga[ee][j2]);
        }
      }
      #pragma unroll
      for (int ee=0;ee<8;ee++){
        #pragma unroll
        for (int j2=0;j2<4;j2++)
          g_sm[ee*1024 + (ccg*4+j2)*32 + w] = ga[ee][j2];
      }
    }
    __syncthreads();
    {
      const float* gbase = g_sm + e*1024 + wbase;
      #pragma unroll 2
      for (int cc=0; cc<32; cc++){
        const int ch = ch0 + cc;
        ulonglong2 wv0 = __ldg(wvp_base + (size_t)ch*256);
        ulonglong2 wv1 = __ldg(wvp_base + (size_t)ch*256 + 1);
        const float* gp = gbase + cc*32;
        #pragma unroll
        for (int k=0;k<8;k++){
          float gv = gp[4*k];
          unsigned long long gd = pk2(gv,gv);
          hacc[0][k] = f2fma(wv0.x, gd, hacc[0][k]);
          hacc[1][k] = f2fma(wv0.y, gd, hacc[1][k]);
          hacc[2][k] = f2fma(wv1.x, gd, hacc[2][k]);
          hacc[3][k] = f2fma(wv1.y, gd, hacc[3][k]);
        }
      }
    }
    __syncthreads();
  }

  // ---- write h to global, ed-major (coalesced in 16B segments)
  {
    const int pixb = b*1024 + hrow*32 + wbase;
    #pragma unroll
    for (int dp=0; dp<4; dp++){
      int ed = e*64 + d0 + 2*dp;
      float* r0 = g_h + (size_t)ed*8192 + pixb;
      float* r1 = r0 + 8192;
      #pragma unroll
      for (int k=0;k<8;k++){
        float lo,hi; upk2(hacc[dp][k],lo,hi);
        r0[4*k] = lo;
        r1[4*k] = hi;
      }
    }
  }
}

// ---------------- kernel2 v2: out[pix, o] = h[pix, :] @ w_out + b_out
// M=8192, N=256, K=512.  Block tile 128M x 64N, grid (64,4), 256 thr.
// Thread tile: m in [8mg, 8mg+8) (4 contiguous m-pairs, 2x LDS128) x 4 n.
// Double-buffered smem: ldg(next) -> fma(cur) -> sts(next) -> bar  (1 barrier/kc)
__global__ __launch_bounds__(256) void out_gemm(const float* __restrict__ w_out,
                                                const float* __restrict__ b_out,
                                                float* __restrict__ out)
{
  __shared__ float a_sm[2][32*128];   // [buf][kk][m]  2x16KB
  __shared__ float b_sm[2][32*64];    // [buf][kk][n]  2x8KB
  const int t = threadIdx.x;
  const int Mbase = blockIdx.x * 128;
  const int Nbase = blockIdx.y * 64;
  const int mg = t & 15, ng = t >> 4;

  unsigned long long acc[4][4];
  #pragma unroll
  for (int j=0;j<4;j++){
    #pragma unroll
    for (int nn=0;nn<4;nn++) acc[j][nn]=0ull;
  }

  float4 ra[4], rb[2];
  // prologue: load chunk 0, stage into buf 0
  #pragma unroll
  for (int i=0;i<4;i++){
    int l = i*256 + t, kk = l >> 5, mf = l & 31;
    ra[i] = __ldg(reinterpret_cast<const float4*>(g_h + (size_t)kk*8192 + Mbase + mf*4));
  }
  #pragma unroll
  for (int i=0;i<2;i++){
    int l = i*256 + t, kk = l >> 4, nf = l & 15;
    rb[i] = __ldg(reinterpret_cast<const float4*>(w_out + (size_t)kk*256 + Nbase + nf*4));
  }
  #pragma unroll
  for (int i=0;i<4;i++){
    int l = i*256 + t, kk = l >> 5, mf = l & 31;
    *reinterpret_cast<float4*>(&a_sm[0][kk*128 + mf*4]) = ra[i];
  }
  #pragma unroll
  for (int i=0;i<2;i++){
    int l = i*256 + t, kk = l >> 4, nf = l & 15;
    *reinterpret_cast<float4*>(&b_sm[0][kk*64 + nf*4]) = rb[i];
  }
  __syncthreads();

  for (int kc=0; kc<16; kc++){
    const int buf = kc & 1;
    // load next chunk into registers (latency hidden under fma block)
    if (kc < 15){
      int k0 = (kc+1)*32;
      #pragma unroll
      for (int i=0;i<4;i++){
        int l = i*256 + t, kk = l >> 5, mf = l & 31;
        ra[i] = __ldg(reinterpret_cast<const float4*>(g_h + (size_t)(k0+kk)*8192 + Mbase + mf*4));
      }
      #pragma unroll
      for (int i=0;i<2;i++){
        int l = i*256 + t, kk = l >> 4, nf = l & 15;
        rb[i] = __ldg(reinterpret_cast<const float4*>(w_out + (size_t)(k0+kk)*256 + Nbase + nf*4));
      }
    }
    // compute on current buffer
    #pragma unroll 4
    for (int kk=0; kk<32; kk++){
      ulonglong2 amA = *reinterpret_cast<const ulonglong2*>(&a_sm[buf][kk*128 + 8*mg]);
      ulonglong2 amB = *reinterpret_cast<const ulonglong2*>(&a_sm[buf][kk*128 + 8*mg + 4]);
      #pragma unroll
      for (int nn=0;nn<4;nn++){
        float bv = b_sm[buf][kk*64 + ng*4 + nn];
        unsigned long long bd = pk2(bv,bv);
        acc[0][nn] = f2fma(amA.x, bd, acc[0][nn]);
        acc[1][nn] = f2fma(amA.y, bd, acc[1][nn]);
        acc[2][nn] = f2fma(amB.x, bd, acc[2][nn]);
        acc[3][nn] = f2fma(amB.y, bd, acc[3][nn]);
      }
    }
    // stage next chunk (other buffer was last read at kc-1; freed by that iteration's barrier)
    if (kc < 15){
      const int nb = buf ^ 1;
      #pragma unroll
      for (int i=0;i<4;i++){
        int l = i*256 + t, kk = l >> 5, mf = l & 31;
        *reinterpret_cast<float4*>(&a_sm[nb][kk*128 + mf*4]) = ra[i];
      }
      #pragma unroll
      for (int i=0;i<2;i++){
        int l = i*256 + t, kk = l >> 4, nf = l & 15;
        *reinterpret_cast<float4*>(&b_sm[nb][kk*64 + nf*4]) = rb[i];
      }
      __syncthreads();
    }
  }

  // store: thread owns 8 consecutive pixels at pl = (Mbase&1023) + 8mg -> 2x STG128 per n
  const int bb = Mbase >> 10;
  const int pl = (Mbase & 1023) + 8*mg;
  #pragma unroll
  for (int nn=0;nn<4;nn++){
    int o = Nbase + ng*4 + nn;
    float bo = __ldg(b_out + o);
    float* op = out + (size_t)bb*262144 + (size_t)o*1024 + pl;
    float v[8];
    #pragma unroll
    for (int j=0;j<4;j++){
      upk2(acc[j][nn], v[2*j], v[2*j+1]);
      v[2*j]   += bo;
      v[2*j+1] += bo;
    }
    *reinterpret_cast<float4*>(op)     = make_float4(v[0],v[1],v[2],v[3]);
    *reinterpret_cast<float4*>(op + 4) = make_float4(v[4],v[5],v[6],v[7]);
  }
}

extern "C" void kernel_launch(void* const* d_in, const int* in_sizes, int n_in,
                              void* d_out, int out_size) {
  const int*   q     = (const int*)  d_in[0];
  const float* c     = (const float*)d_in[1];
  const float* rms_w = (const float*)d_in[2];
  const float* emb   = (const float*)d_in[3];
  const float* w1    = (const float*)d_in[4];
  const float* b1    = (const float*)d_in[5];
  const float* w2    = (const float*)d_in[6];
  const float* b2    = (const float*)d_in[7];
  const float* w_kv  = (const float*)d_in[8];
  const float* w_out = (const float*)d_in[9];
  const float* b_out = (const float*)d_in[10];
  float* out = (float*)d_out;

  setup_s1<<<dim3(BB, 8), 256>>>(q, emb, w1, b1);
  setup_qh<<<dim3(BB, 8), 256>>>(w2, b2);
  setup_u <<<dim3(BB, NH), 256>>>(w_kv, rms_w);

  int smem_bytes = 18944 * 4;  // 75.8KB -> 2 blocks/SM
  cudaFuncSetAttribute(main_kernel, cudaFuncAttributeMaxDynamicSharedMemorySize, smem_bytes);
  main_kernel<<<256, 256, smem_bytes>>>(c, rms_w, w_kv);

  out_gemm<<<dim3(64, 4), 256>>>(w_out, b_out, out);
}

// round 14
// speedup vs baseline: 1.1565x; 1.1565x over previous
#include <cuda_runtime.h>
#include <cstdint>
#include <cstdio>

#define HID 256
#define HS  512
#define NH  8
#define HD  64
#define NTOK 8
#define BB  8

__device__ float g_u[BB][NH][HID];
__device__ float g_s1[BB][HS];
__device__ float g_qh[BB][HS];
// Intermediate h, ed-major: g_h[ed][pix], pix = b*1024 + hrow*32 + w.  16.8 MB
__device__ float g_h[HS * 8192];

static __device__ __forceinline__ unsigned long long pk2(float lo, float hi){
  unsigned long long r; asm("mov.b64 %0, {%1,%2};" : "=l"(r) : "f"(lo), "f"(hi)); return r;
}
static __device__ __forceinline__ void upk2(unsigned long long v, float& lo, float& hi){
  asm("mov.b64 {%0,%1}, %2;" : "=f"(lo), "=f"(hi) : "l"(v));
}
static __device__ __forceinline__ unsigned long long f2fma(unsigned long long a, unsigned long long b, unsigned long long c){
  unsigned long long d; asm("fma.rn.f32x2 %0, %1, %2, %3;" : "=l"(d) : "l"(a), "l"(b), "l"(c)); return d;
}

// ---------------- setup stage 1: s1 = silu(emb[q] @ w1 + b1)   grid (8 b, 8 slice), 256 thr
__global__ void setup_s1(const int* __restrict__ q, const float* __restrict__ emb,
                         const float* __restrict__ w1, const float* __restrict__ b1)
{
  __shared__ float red[4][64];
  __shared__ float qe[HID];
  const int b = blockIdx.x, slice = blockIdx.y, t = threadIdx.x;
  if (t < HID) qe[t] = __ldg(emb + (size_t)__ldg(q + b)*HID + t);
  __syncthreads();
  const int cl = t & 63, qq = t >> 6;
  const int col = slice*64 + cl;
  const float* wcol = w1 + col;
  float a0=0.f, a1=0.f;
  const int i0 = qq*64;
  #pragma unroll 8
  for (int i=0; i<64; i+=2){
    a0 = fmaf(qe[i0+i  ], __ldg(wcol + (size_t)(i0+i  )*HS), a0);
    a1 = fmaf(qe[i0+i+1], __ldg(wcol + (size_t)(i0+i+1)*HS), a1);
  }
  red[qq][cl] = a0 + a1;
  __syncthreads();
  if (t < 64){
    float s = red[0][t]+red[1][t]+red[2][t]+red[3][t] + __ldg(b1 + slice*64 + t);
    g_s1[b][slice*64+t] = s / (1.f + expf(-s));
  }
}

// ---------------- setup stage 2: qh = s1 @ w2 + b2   grid (8 b, 8 slice), 256 thr
__global__ void setup_qh(const float* __restrict__ w2, const float* __restrict__ b2)
{
  __shared__ float red[4][64];
  __shared__ float s1s[HS];
  const int b = blockIdx.x, slice = blockIdx.y, t = threadIdx.x;
  s1s[t]     = g_s1[b][t];
  s1s[t+256] = g_s1[b][t+256];
  __syncthreads();
  const int cl = t & 63, qq = t >> 6;
  const int col = slice*64 + cl;
  const float* wcol = w2 + col;
  float a0=0.f, a1=0.f;
  const int i0 = qq*128;
  #pragma unroll 8
  for (int i=0; i<128; i+=2){
    a0 = fmaf(s1s[i0+i  ], __ldg(wcol + (size_t)(i0+i  )*HS), a0);
    a1 = fmaf(s1s[i0+i+1], __ldg(wcol + (size_t)(i0+i+1)*HS), a1);
  }
  red[qq][cl] = a0 + a1;
  __syncthreads();
  if (t < 64)
    g_qh[b][slice*64+t] = red[0][t]+red[1][t]+red[2][t]+red[3][t] + __ldg(b2 + slice*64 + t);
}

// ---------------- setup stage 3: u[b][e][ch] = (w_kv_k[ch,e,:] . qh[b,e,:]) * rms_w[ch]/8
__global__ void setup_u(const float* __restrict__ w_kv, const float* __restrict__ rms_w)
{
  __shared__ float qh_sm[64];
  const int b = blockIdx.x, e = blockIdx.y, t = threadIdx.x;
  if (t < 64) qh_sm[t] = g_qh[b][e*64 + t];
  __syncthreads();
  const float4* wk = reinterpret_cast<const float4*>(w_kv + (size_t)t*1024 + e*128);
  float a0=0.f, a1=0.f;
  #pragma unroll
  for (int j=0; j<16; j+=2){
    float4 v0 = __ldg(wk + j);
    float4 v1 = __ldg(wk + j + 1);
    a0 = fmaf(qh_sm[4*j+0], v0.x, a0);
    a0 = fmaf(qh_sm[4*j+1], v0.y, a0);
    a0 = fmaf(qh_sm[4*j+2], v0.z, a0);
    a0 = fmaf(qh_sm[4*j+3], v0.w, a0);
    a1 = fmaf(qh_sm[4*j+4], v1.x, a1);
    a1 = fmaf(qh_sm[4*j+5], v1.y, a1);
    a1 = fmaf(qh_sm[4*j+6], v1.z, a1);
    a1 = fmaf(qh_sm[4*j+7], v1.w, a1);
  }
  g_u[b][e][t] = (a0+a1) * __ldg(rms_w + t) * 0.125f;
}

// ---------------- kernel1: pass1 + softmax + g + h -> g_h (ed-major)
// smem (floats), 18944 total = 75.8KB -> 2 blocks/SM:
//  [0,256) rms | [256,512) rinv | [512,2560) attn | [2560,10752) cn (ur aliases) | [10752,18944) g
__global__ __launch_bounds__(256, 2) void main_kernel(const float* __restrict__ c,
    const float* __restrict__ rms_w, const float* __restrict__ w_kv)
{
  extern __shared__ float sm[];
  float* rms_sm  = sm;
  float* rinv_sm = sm + 256;
  float* attn_sm = sm + 512;
  float* cn_sm   = sm + 2560;
  float* ur_sm   = sm + 2560;   // alias (dead once chunk loop starts)
  float* g_sm    = sm + 10752;

  const int t  = threadIdx.x;
  const int bx = blockIdx.x;
  const int b  = bx >> 5, hrow = bx & 31;
  const int w  = t & 31;
  const int n  = t >> 5;        // warp id
  const int lane = w;

  rms_sm[t] = rms_w[t];
  {
    int ch = t;
    #pragma unroll
    for (int e=0;e<NH;e++) ur_sm[ch*NH + e] = g_u[b][e][ch];
  }
  __syncthreads();

  const float* cp = c + ((size_t)(b*NTOK + n)*HID)*1024 + hrow*32 + w;

  // ---- pass 1: stream c once (unroll-8 batched loads); rms sum + 8 head dots
  float ss = 0.f;
  unsigned long long s2[4];
  s2[0]=s2[1]=s2[2]=s2[3]=0ull;
  const unsigned long long* urp = reinterpret_cast<const unsigned long long*>(ur_sm);
  for (int c8=0; c8<32; c8++){
    float x[8];
    #pragma unroll
    for (int j=0;j<8;j++) x[j] = __ldg(cp + (size_t)(c8*8+j)*1024);
    #pragma unroll
    for (int j=0;j<8;j++){
      unsigned long long xd = pk2(x[j],x[j]);
      int ch = c8*8+j;
      ss = fmaf(x[j],x[j],ss);
      s2[0] = f2fma(xd, urp[ch*4+0], s2[0]);
      s2[1] = f2fma(xd, urp[ch*4+1], s2[1]);
      s2[2] = f2fma(xd, urp[ch*4+2], s2[2]);
      s2[3] = f2fma(xd, urp[ch*4+3], s2[3]);
    }
  }
  float rinv = rsqrtf(ss*(1.f/256.f) + 1e-6f);
  rinv_sm[n*32+w] = rinv;
  #pragma unroll
  for (int j=0;j<4;j++){
    float lo,hi; upk2(s2[j],lo,hi);
    attn_sm[(2*j  )*256 + n*32 + w] = lo*rinv;
    attn_sm[(2*j+1)*256 + n*32 + w] = hi*rinv;
  }
  __syncthreads();

  // ---- softmax over n: thread (e = n-slot, w)
  {
    int e = n;
    float d[8], m = -1e30f;
    #pragma unroll
    for (int i=0;i<8;i++){ d[i] = attn_sm[e*256 + i*32 + w]; m = fmaxf(m,d[i]); }
    float ssum = 0.f;
    #pragma unroll
    for (int i=0;i<8;i++){ d[i] = __expf(d[i]-m); ssum += d[i]; }
    float inv = 1.f/ssum;
    #pragma unroll
    for (int i=0;i<8;i++) attn_sm[e*256 + i*32 + w] = d[i]*inv;
  }
  __syncthreads();

  // ---- chunk loop: stage cn, compute g, accumulate h in registers
  // h-phase tile: warp = head e; thread (dg = lane&7, wpg = lane>>3):
  //   d in [dg*8, dg*8+8) (8 scalars, dup'd), 4 consecutive w-PAIRS (pixels 8wpg..8wpg+7)
  const int e   = n;
  const int dg  = lane & 7;
  const int wpg = lane >> 3;            // 0..3
  const int d0  = dg * 8;
  unsigned long long hacc[8][4];        // [d][k], k = pixel pair (8wpg+2k, +1)
  #pragma unroll
  for (int i=0;i<8;i++){
    #pragma unroll
    for (int k=0;k<4;k++) hacc[i][k]=0ull;
  }
  const float4* wv4 =
      reinterpret_cast<const float4*>(w_kv + e*128 + 64 + d0);  // + ch*256 float4 per row

  for (int kc=0; kc<8; kc++){
    const int ch0 = kc*32;
    {
      #pragma unroll 4
      for (int cc=0; cc<32; cc++){
        float x = __ldg(cp + (size_t)(ch0+cc)*1024);
        cn_sm[n*1024 + cc*32 + w] = x * rinv * rms_sm[ch0+cc];
      }
    }
    __syncthreads();
    {
      int ccg = n;
      float ga[8][4];
      #pragma unroll
      for (int i=0;i<8;i++){
        #pragma unroll
        for (int j2=0;j2<4;j2++) ga[i][j2]=0.f;
      }
      #pragma unroll
      for (int nn=0; nn<8; nn++){
        float a[8];
        #pragma unroll
        for (int ee=0;ee<8;ee++) a[ee] = attn_sm[ee*256 + nn*32 + w];
        #pragma unroll
        for (int j2=0;j2<4;j2++){
          float cv = cn_sm[nn*1024 + (ccg*4+j2)*32 + w];
          #pragma unroll
          for (int ee=0;ee<8;ee++) ga[ee][j2] = fmaf(a[ee], cv, ga[ee][j2]);
        }
      }
      #pragma unroll
      for (int ee=0;ee<8;ee++){
        #pragma unroll
        for (int j2=0;j2<4;j2++)
          g_sm[ee*1024 + (ccg*4+j2)*32 + w] = ga[ee][j2];
      }
    }
    __syncthreads();
    // h-phase: per cc = 2 LDG128 (8 d weights) + 8 pk2 (dup) + 4 LDS64 (native w-pairs) + 32 FFMA2
    {
      const unsigned long long* gbase =
          reinterpret_cast<const unsigned long long*>(g_sm + e*1024) + 4*wpg;
      #pragma unroll 2
      for (int cc=0; cc<32; cc++){
        const int ch = ch0 + cc;
        float4 fa = __ldg(wv4 + (size_t)ch*256);
        float4 fb = __ldg(wv4 + (size_t)ch*256 + 1);
        const unsigned long long* gp = gbase + cc*16;
        unsigned long long g0 = gp[0], g1 = gp[1], g2v = gp[2], g3 = gp[3];
        unsigned long long wd0 = pk2(fa.x,fa.x), wd1 = pk2(fa.y,fa.y);
        unsigned long long wd2 = pk2(fa.z,fa.z), wd3 = pk2(fa.w,fa.w);
        unsigned long long wd4 = pk2(fb.x,fb.x), wd5 = pk2(fb.y,fb.y);
        unsigned long long wd6 = pk2(fb.z,fb.z), wd7 = pk2(fb.w,fb.w);
        hacc[0][0]=f2fma(wd0,g0,hacc[0][0]); hacc[0][1]=f2fma(wd0,g1,hacc[0][1]);
        hacc[0][2]=f2fma(wd0,g2v,hacc[0][2]); hacc[0][3]=f2fma(wd0,g3,hacc[0][3]);
        hacc[1][0]=f2fma(wd1,g0,hacc[1][0]); hacc[1][1]=f2fma(wd1,g1,hacc[1][1]);
        hacc[1][2]=f2fma(wd1,g2v,hacc[1][2]); hacc[1][3]=f2fma(wd1,g3,hacc[1][3]);
        hacc[2][0]=f2fma(wd2,g0,hacc[2][0]); hacc[2][1]=f2fma(wd2,g1,hacc[2][1]);
        hacc[2][2]=f2fma(wd2,g2v,hacc[2][2]); hacc[2][3]=f2fma(wd2,g3,hacc[2][3]);
        hacc[3][0]=f2fma(wd3,g0,hacc[3][0]); hacc[3][1]=f2fma(wd3,g1,hacc[3][1]);
        hacc[3][2]=f2fma(wd3,g2v,hacc[3][2]); hacc[3][3]=f2fma(wd3,g3,hacc[3][3]);
        hacc[4][0]=f2fma(wd4,g0,hacc[4][0]); hacc[4][1]=f2fma(wd4,g1,hacc[4][1]);
        hacc[4][2]=f2fma(wd4,g2v,hacc[4][2]); hacc[4][3]=f2fma(wd4,g3,hacc[4][3]);
        hacc[5][0]=f2fma(wd5,g0,hacc[5][0]); hacc[5][1]=f2fma(wd5,g1,hacc[5][1]);
        hacc[5][2]=f2fma(wd5,g2v,hacc[5][2]); hacc[5][3]=f2fma(wd5,g3,hacc[5][3]);
        hacc[6][0]=f2fma(wd6,g0,hacc[6][0]); hacc[6][1]=f2fma(wd6,g1,hacc[6][1]);
        hacc[6][2]=f2fma(wd6,g2v,hacc[6][2]); hacc[6][3]=f2fma(wd6,g3,hacc[6][3]);
        hacc[7][0]=f2fma(wd7,g0,hacc[7][0]); hacc[7][1]=f2fma(wd7,g1,hacc[7][1]);
        hacc[7][2]=f2fma(wd7,g2v,hacc[7][2]); hacc[7][3]=f2fma(wd7,g3,hacc[7][3]);
      }
    }
    __syncthreads();
  }

  // ---- write h to global, ed-major: 8 consecutive pixels per thread -> 2x STG128 per d row
  {
    const int pixb = b*1024 + hrow*32 + 8*wpg;
    #pragma unroll
    for (int d=0; d<8; d++){
      int ed = e*64 + d0 + d;
      float* r = g_h + (size_t)ed*8192 + pixb;
      ulonglong2 v0; v0.x = hacc[d][0]; v0.y = hacc[d][1];
      ulonglong2 v1; v1.x = hacc[d][2]; v1.y = hacc[d][3];
      *reinterpret_cast<ulonglong2*>(r)     = v0;
      *reinterpret_cast<ulonglong2*>(r + 4) = v1;
    }
  }
}

// ---------------- kernel2 (R10, FROZEN): out[pix, o] = h[pix, :] @ w_out + b_out
// M=8192, N=256, K=512.  Block tile 128M x 64N, grid (64, 4), 256 threads.
__global__ __launch_bounds__(256) void out_gemm(const float* __restrict__ w_out,
                                                const float* __restrict__ b_out,
                                                float* __restrict__ out)
{
  __shared__ float a_sm[32*128];   // [kk][m]
  __shared__ float b_sm[32*64];    // [kk][n]
  const int t = threadIdx.x;
  const int Mbase = blockIdx.x * 128;
  const int Nbase = blockIdx.y * 64;
  const int mg = t & 15, ng = t >> 4;

  unsigned long long acc[4][4];
  #pragma unroll
  for (int j=0;j<4;j++){
    #pragma unroll
    for (int nn=0;nn<4;nn++) acc[j][nn]=0ull;
  }

  float4 ra[4], rb[2];
  #pragma unroll
  for (int i=0;i<4;i++){
    int l = i*256 + t, kk = l >> 5, mf = l & 31;
    ra[i] = __ldg(reinterpret_cast<const float4*>(g_h + (size_t)kk*8192 + Mbase + mf*4));
  }
  #pragma unroll
  for (int i=0;i<2;i++){
    int l = i*256 + t, kk = l >> 4, nf = l & 15;
    rb[i] = __ldg(reinterpret_cast<const float4*>(w_out + (size_t)kk*256 + Nbase + nf*4));
  }

  for (int kc=0; kc<16; kc++){
    #pragma unroll
    for (int i=0;i<4;i++){
      int l = i*256 + t, kk = l >> 5, mf = l & 31;
      *reinterpret_cast<float4*>(a_sm + kk*128 + mf*4) = ra[i];
    }
    #pragma unroll
    for (int i=0;i<2;i++){
      int l = i*256 + t, kk = l >> 4, nf = l & 15;
      *reinterpret_cast<float4*>(b_sm + kk*64 + nf*4) = rb[i];
    }
    __syncthreads();
    if (kc < 15){
      int k0 = (kc+1)*32;
      #pragma unroll
      for (int i=0;i<4;i++){
        int l = i*256 + t, kk = l >> 5, mf = l & 31;
        ra[i] = __ldg(reinterpret_cast<const float4*>(g_h + (size_t)(k0+kk)*8192 + Mbase + mf*4));
      }
      #pragma unroll
      for (int i=0;i<2;i++){
        int l = i*256 + t, kk = l >> 4, nf = l & 15;
        rb[i] = __ldg(reinterpret_cast<const float4*>(w_out + (size_t)(k0+kk)*256 + Nbase + nf*4));
      }
    }
    #pragma unroll 4
    for (int kk=0; kk<32; kk++){
      unsigned long long am[4];
      #pragma unroll
      for (int j=0;j<4;j++)
        am[j] = *reinterpret_cast<const unsigned long long*>(a_sm + kk*128 + 2*mg + 32*j);
      #pragma unroll
      for (int nn=0;nn<4;nn++){
        float bv = b_sm[kk*64 + ng*4 + nn];
        unsigned long long bd = pk2(bv,bv);
        #pragma unroll
        for (int j=0;j<4;j++) acc[j][nn] = f2fma(am[j], bd, acc[j][nn]);
      }
    }
    __syncthreads();
  }

  const int bb = Mbase >> 10;
  const int pl = (Mbase & 1023) + 2*mg;
  #pragma unroll
  for (int nn=0;nn<4;nn++){
    int o = Nbase + ng*4 + nn;
    float bo = __ldg(b_out + o);
    float* op = out + (size_t)bb*262144 + (size_t)o*1024 + pl;
    #pragma unroll
    for (int j=0;j<4;j++){
      float lo,hi; upk2(acc[j][nn],lo,hi);
      float2 v = make_float2(lo+bo, hi+bo);
      *reinterpret_cast<float2*>(op + 32*j) = v;
    }
  }
}

extern "C" void kernel_launch(void* const* d_in, const int* in_sizes, int n_in,
                              void* d_out, int out_size) {
  const int*   q     = (const int*)  d_in[0];
  const float* c     = (const float*)d_in[1];
  const float* rms_w = (const float*)d_in[2];
  const float* emb   = (const float*)d_in[3];
  const float* w1    = (const float*)d_in[4];
  const float* b1    = (const float*)d_in[5];
  const float* w2    = (const float*)d_in[6];
  const float* b2    = (const float*)d_in[7];
  const float* w_kv  = (const float*)d_in[8];
  const float* w_out = (const float*)d_in[9];
  const float* b_out = (const float*)d_in[10];
  float* out = (float*)d_out;

  setup_s1<<<dim3(BB, 8), 256>>>(q, emb, w1, b1);
  setup_qh<<<dim3(BB, 8), 256>>>(w2, b2);
  setup_u <<<dim3(BB, NH), 256>>>(w_kv, rms_w);

  int smem_bytes = 18944 * 4;  // 75.8KB -> 2 blocks/SM
  cudaFuncSetAttribute(main_kernel, cudaFuncAttributeMaxDynamicSharedMemorySize, smem_bytes);
  main_kernel<<<256, 256, smem_bytes>>>(c, rms_w, w_kv);

  out_gemm<<<dim3(64, 4), 256>>>(w_out, b_out, out);
}

// round 15
// speedup vs baseline: 1.2252x; 1.0595x over previous
#include <cuda_runtime.h>
#include <cstdint>
#include <cstdio>

#define HID 256
#define HS  512
#define NH  8
#define HD  64
#define NTOK 8
#define BB  8

__device__ float g_u[BB][NH][HID];
__device__ float g_s1[BB][HS];
__device__ float g_qh[BB][HS];
// Intermediate h, ed-major: g_h[ed][pix], pix = b*1024 + hrow*32 + w.  16.8 MB
__device__ float g_h[HS * 8192];

static __device__ __forceinline__ unsigned long long pk2(float lo, float hi){
  unsigned long long r; asm("mov.b64 %0, {%1,%2};" : "=l"(r) : "f"(lo), "f"(hi)); return r;
}
static __device__ __forceinline__ void upk2(unsigned long long v, float& lo, float& hi){
  asm("mov.b64 {%0,%1}, %2;" : "=f"(lo), "=f"(hi) : "l"(v));
}
static __device__ __forceinline__ unsigned long long f2fma(unsigned long long a, unsigned long long b, unsigned long long c){
  unsigned long long d; asm("fma.rn.f32x2 %0, %1, %2, %3;" : "=l"(d) : "l"(a), "l"(b), "l"(c)); return d;
}
static __device__ __forceinline__ unsigned long long f2mul(unsigned long long a, unsigned long long b){
  unsigned long long d; asm("mul.rn.f32x2 %0, %1, %2;" : "=l"(d) : "l"(a), "l"(b)); return d;
}

// ---------------- setup stage 1: s1 = silu(emb[q] @ w1 + b1)   grid (8 b, 8 slice), 256 thr
__global__ void setup_s1(const int* __restrict__ q, const float* __restrict__ emb,
                         const float* __restrict__ w1, const float* __restrict__ b1)
{
  __shared__ float red[4][64];
  __shared__ float qe[HID];
  const int b = blockIdx.x, slice = blockIdx.y, t = threadIdx.x;
  if (t < HID) qe[t] = __ldg(emb + (size_t)__ldg(q + b)*HID + t);
  __syncthreads();
  const int cl = t & 63, qq = t >> 6;
  const int col = slice*64 + cl;
  const float* wcol = w1 + col;
  float a0=0.f, a1=0.f;
  const int i0 = qq*64;
  #pragma unroll 8
  for (int i=0; i<64; i+=2){
    a0 = fmaf(qe[i0+i  ], __ldg(wcol + (size_t)(i0+i  )*HS), a0);
    a1 = fmaf(qe[i0+i+1], __ldg(wcol + (size_t)(i0+i+1)*HS), a1);
  }
  red[qq][cl] = a0 + a1;
  __syncthreads();
  if (t < 64){
    float s = red[0][t]+red[1][t]+red[2][t]+red[3][t] + __ldg(b1 + slice*64 + t);
    g_s1[b][slice*64+t] = s / (1.f + expf(-s));
  }
}

// ---------------- setup stage 2: qh = s1 @ w2 + b2   grid (8 b, 8 slice), 256 thr
__global__ void setup_qh(const float* __restrict__ w2, const float* __restrict__ b2)
{
  __shared__ float red[4][64];
  __shared__ float s1s[HS];
  const int b = blockIdx.x, slice = blockIdx.y, t = threadIdx.x;
  s1s[t]     = g_s1[b][t];
  s1s[t+256] = g_s1[b][t+256];
  __syncthreads();
  const int cl = t & 63, qq = t >> 6;
  const int col = slice*64 + cl;
  const float* wcol = w2 + col;
  float a0=0.f, a1=0.f;
  const int i0 = qq*128;
  #pragma unroll 8
  for (int i=0; i<128; i+=2){
    a0 = fmaf(s1s[i0+i  ], __ldg(wcol + (size_t)(i0+i  )*HS), a0);
    a1 = fmaf(s1s[i0+i+1], __ldg(wcol + (size_t)(i0+i+1)*HS), a1);
  }
  red[qq][cl] = a0 + a1;
  __syncthreads();
  if (t < 64)
    g_qh[b][slice*64+t] = red[0][t]+red[1][t]+red[2][t]+red[3][t] + __ldg(b2 + slice*64 + t);
}

// ---------------- setup stage 3: u[b][e][ch] = (w_kv_k[ch,e,:] . qh[b,e,:]) * rms_w[ch]/8
__global__ void setup_u(const float* __restrict__ w_kv, const float* __restrict__ rms_w)
{
  __shared__ float qh_sm[64];
  const int b = blockIdx.x, e = blockIdx.y, t = threadIdx.x;
  if (t < 64) qh_sm[t] = g_qh[b][e*64 + t];
  __syncthreads();
  const float4* wk = reinterpret_cast<const float4*>(w_kv + (size_t)t*1024 + e*128);
  float a0=0.f, a1=0.f;
  #pragma unroll
  for (int j=0; j<16; j+=2){
    float4 v0 = __ldg(wk + j);
    float4 v1 = __ldg(wk + j + 1);
    a0 = fmaf(qh_sm[4*j+0], v0.x, a0);
    a0 = fmaf(qh_sm[4*j+1], v0.y, a0);
    a0 = fmaf(qh_sm[4*j+2], v0.z, a0);
    a0 = fmaf(qh_sm[4*j+3], v0.w, a0);
    a1 = fmaf(qh_sm[4*j+4], v1.x, a1);
    a1 = fmaf(qh_sm[4*j+5], v1.y, a1);
    a1 = fmaf(qh_sm[4*j+6], v1.z, a1);
    a1 = fmaf(qh_sm[4*j+7], v1.w, a1);
  }
  g_u[b][e][t] = (a0+a1) * __ldg(rms_w + t) * 0.125f;
}

// ---------------- kernel1: pass1 + softmax + g + h -> g_h (ed-major)
// smem (floats), 18944 total = 75.8KB -> 2 blocks/SM:
//  [0,256) rms | [256,512) rinv | [512,2560) attn | [2560,10752) cn (ur aliases) | [10752,18944) g
__global__ __launch_bounds__(256, 2) void main_kernel(const float* __restrict__ c,
    const float* __restrict__ rms_w, const float* __restrict__ w_kv)
{
  extern __shared__ float sm[];
  float* rms_sm  = sm;
  float* rinv_sm = sm + 256;
  float* attn_sm = sm + 512;
  float* cn_sm   = sm + 2560;
  float* ur_sm   = sm + 2560;   // alias (dead once chunk loop starts)
  float* g_sm    = sm + 10752;

  const int t  = threadIdx.x;
  const int bx = blockIdx.x;
  const int b  = bx >> 5, hrow = bx & 31;
  const int w  = t & 31;
  const int n  = t >> 5;        // warp id
  const int lane = w;

  rms_sm[t] = rms_w[t];
  {
    int ch = t;
    #pragma unroll
    for (int e=0;e<NH;e++) ur_sm[ch*NH + e] = g_u[b][e][ch];
  }
  __syncthreads();

  const float* cp = c + ((size_t)(b*NTOK + n)*HID)*1024 + hrow*32 + w;

  // ---- pass 1: stream c once (unroll-8 batched loads); rms sum + 8 head dots
  float ss = 0.f;
  unsigned long long s2[4];
  s2[0]=s2[1]=s2[2]=s2[3]=0ull;
  const unsigned long long* urp = reinterpret_cast<const unsigned long long*>(ur_sm);
  for (int c8=0; c8<32; c8++){
    float x[8];
    #pragma unroll
    for (int j=0;j<8;j++) x[j] = __ldg(cp + (size_t)(c8*8+j)*1024);
    #pragma unroll
    for (int j=0;j<8;j++){
      unsigned long long xd = pk2(x[j],x[j]);
      int ch = c8*8+j;
      ss = fmaf(x[j],x[j],ss);
      s2[0] = f2fma(xd, urp[ch*4+0], s2[0]);
      s2[1] = f2fma(xd, urp[ch*4+1], s2[1]);
      s2[2] = f2fma(xd, urp[ch*4+2], s2[2]);
      s2[3] = f2fma(xd, urp[ch*4+3], s2[3]);
    }
  }
  float rinv = rsqrtf(ss*(1.f/256.f) + 1e-6f);
  rinv_sm[n*32+w] = rinv;
  #pragma unroll
  for (int j=0;j<4;j++){
    float lo,hi; upk2(s2[j],lo,hi);
    attn_sm[(2*j  )*256 + n*32 + w] = lo*rinv;
    attn_sm[(2*j+1)*256 + n*32 + w] = hi*rinv;
  }
  __syncthreads();

  // ---- softmax over n: thread (e = n-slot, w)
  {
    int e = n;
    float d[8], m = -1e30f;
    #pragma unroll
    for (int i=0;i<8;i++){ d[i] = attn_sm[e*256 + i*32 + w]; m = fmaxf(m,d[i]); }
    float ssum = 0.f;
    #pragma unroll
    for (int i=0;i<8;i++){ d[i] = __expf(d[i]-m); ssum += d[i]; }
    float inv = 1.f/ssum;
    #pragma unroll
    for (int i=0;i<8;i++) attn_sm[e*256 + i*32 + w] = d[i]*inv;
  }
  __syncthreads();

  // ---- cn-stage vector remap: lane = (pq = lane&7 pixel-quad, cb = lane>>3 cc-block)
  const int pq = lane & 7;
  const int cb = lane >> 3;
  // rinv for this lane's 4 pixels as 2 packed u64 (loop-invariant across chunks)
  unsigned long long rp0, rp1;
  {
    const unsigned long long* rq =
        reinterpret_cast<const unsigned long long*>(rinv_sm + n*32 + 4*pq);
    rp0 = rq[0];
    rp1 = rq[1];
  }
  // c base for this lane's pixel quad (token n)
  const float4* c4 = reinterpret_cast<const float4*>(
      c + ((size_t)(b*NTOK + n)*HID)*1024 + hrow*32 + 4*pq);   // + ch*256 float4 per channel

  // ---- chunk loop: stage cn (vectorized), compute g, accumulate h in registers
  // h-phase tile: warp = head e; thread (dg = lane&7, wpg = lane>>3):
  //   d in [dg*8, dg*8+8) (8 scalars, dup'd), 4 consecutive w-PAIRS (pixels 8wpg..8wpg+7)
  const int e   = n;
  const int dg  = lane & 7;
  const int wpg = lane >> 3;            // 0..3
  const int d0  = dg * 8;
  unsigned long long hacc[8][4];        // [d][k], k = pixel pair (8wpg+2k, +1)
  #pragma unroll
  for (int i=0;i<8;i++){
    #pragma unroll
    for (int k=0;k<4;k++) hacc[i][k]=0ull;
  }
  const float4* wv4 =
      reinterpret_cast<const float4*>(w_kv + e*128 + 64 + d0);  // + ch*256 float4 per row

  for (int kc=0; kc<8; kc++){
    const int ch0 = kc*32;
    // stage normalized c chunk, vectorized: 8 iters, each = LDG128 + 4 f32x2 mul + STS128
    {
      #pragma unroll
      for (int i=0; i<8; i++){
        const int cc = cb*8 + i;
        float4 x4 = __ldg(c4 + (size_t)(ch0+cc)*256);
        float rmsv = rms_sm[ch0+cc];
        unsigned long long rmsd = pk2(rmsv, rmsv);
        unsigned long long x01 = pk2(x4.x, x4.y);
        unsigned long long x23 = pk2(x4.z, x4.w);
        unsigned long long cn01 = f2mul(f2mul(x01, rp0), rmsd);
        unsigned long long cn23 = f2mul(f2mul(x23, rp1), rmsd);
        ulonglong2 v; v.x = cn01; v.y = cn23;
        *reinterpret_cast<ulonglong2*>(cn_sm + n*1024 + cc*32 + 4*pq) = v;
      }
    }
    __syncthreads();
    {
      int ccg = n;
      float ga[8][4];
      #pragma unroll
      for (int i=0;i<8;i++){
        #pragma unroll
        for (int j2=0;j2<4;j2++) ga[i][j2]=0.f;
      }
      #pragma unroll
      for (int nn=0; nn<8; nn++){
        float a[8];
        #pragma unroll
        for (int ee=0;ee<8;ee++) a[ee] = attn_sm[ee*256 + nn*32 + w];
        #pragma unroll
        for (int j2=0;j2<4;j2++){
          float cv = cn_sm[nn*1024 + (ccg*4+j2)*32 + w];
          #pragma unroll
          for (int ee=0;ee<8;ee++) ga[ee][j2] = fmaf(a[ee], cv, ga[ee][j2]);
        }
      }
      #pragma unroll
      for (int ee=0;ee<8;ee++){
        #pragma unroll
        for (int j2=0;j2<4;j2++)
          g_sm[ee*1024 + (ccg*4+j2)*32 + w] = ga[ee][j2];
      }
    }
    __syncthreads();
    // h-phase: per cc = 2 LDG128 (8 d weights) + 8 pk2 (dup) + 4 LDS64 (native w-pairs) + 32 FFMA2
    {
      const unsigned long long* gbase =
          reinterpret_cast<const unsigned long long*>(g_sm + e*1024) + 4*wpg;
      #pragma unroll 2
      for (int cc=0; cc<32; cc++){
        const int ch = ch0 + cc;
        float4 fa = __ldg(wv4 + (size_t)ch*256);
        float4 fb = __ldg(wv4 + (size_t)ch*256 + 1);
        const unsigned long long* gp = gbase + cc*16;
        unsigned long long g0 = gp[0], g1 = gp[1], g2v = gp[2], g3 = gp[3];
        unsigned long long wd0 = pk2(fa.x,fa.x), wd1 = pk2(fa.y,fa.y);
        unsigned long long wd2 = pk2(fa.z,fa.z), wd3 = pk2(fa.w,fa.w);
        unsigned long long wd4 = pk2(fb.x,fb.x), wd5 = pk2(fb.y,fb.y);
        unsigned long long wd6 = pk2(fb.z,fb.z), wd7 = pk2(fb.w,fb.w);
        hacc[0][0]=f2fma(wd0,g0,hacc[0][0]); hacc[0][1]=f2fma(wd0,g1,hacc[0][1]);
        hacc[0][2]=f2fma(wd0,g2v,hacc[0][2]); hacc[0][3]=f2fma(wd0,g3,hacc[0][3]);
        hacc[1][0]=f2fma(wd1,g0,hacc[1][0]); hacc[1][1]=f2fma(wd1,g1,hacc[1][1]);
        hacc[1][2]=f2fma(wd1,g2v,hacc[1][2]); hacc[1][3]=f2fma(wd1,g3,hacc[1][3]);
        hacc[2][0]=f2fma(wd2,g0,hacc[2][0]); hacc[2][1]=f2fma(wd2,g1,hacc[2][1]);
        hacc[2][2]=f2fma(wd2,g2v,hacc[2][2]); hacc[2][3]=f2fma(wd2,g3,hacc[2][3]);
        hacc[3][0]=f2fma(wd3,g0,hacc[3][0]); hacc[3][1]=f2fma(wd3,g1,hacc[3][1]);
        hacc[3][2]=f2fma(wd3,g2v,hacc[3][2]); hacc[3][3]=f2fma(wd3,g3,hacc[3][3]);
        hacc[4][0]=f2fma(wd4,g0,hacc[4][0]); hacc[4][1]=f2fma(wd4,g1,hacc[4][1]);
        hacc[4][2]=f2fma(wd4,g2v,hacc[4][2]); hacc[4][3]=f2fma(wd4,g3,hacc[4][3]);
        hacc[5][0]=f2fma(wd5,g0,hacc[5][0]); hacc[5][1]=f2fma(wd5,g1,hacc[5][1]);
        hacc[5][2]=f2fma(wd5,g2v,hacc[5][2]); hacc[5][3]=f2fma(wd5,g3,hacc[5][3]);
        hacc[6][0]=f2fma(wd6,g0,hacc[6][0]); hacc[6][1]=f2fma(wd6,g1,hacc[6][1]);
        hacc[6][2]=f2fma(wd6,g2v,hacc[6][2]); hacc[6][3]=f2fma(wd6,g3,hacc[6][3]);
        hacc[7][0]=f2fma(wd7,g0,hacc[7][0]); hacc[7][1]=f2fma(wd7,g1,hacc[7][1]);
        hacc[7][2]=f2fma(wd7,g2v,hacc[7][2]); hacc[7][3]=f2fma(wd7,g3,hacc[7][3]);
      }
    }
    __syncthreads();
  }

  // ---- write h to global, ed-major: 8 consecutive pixels per thread -> 2x STG128 per d row
  {
    const int pixb = b*1024 + hrow*32 + 8*wpg;
    #pragma unroll
    for (int d=0; d<8; d++){
      int ed = e*64 + d0 + d;
      float* r = g_h + (size_t)ed*8192 + pixb;
      ulonglong2 v0; v0.x = hacc[d][0]; v0.y = hacc[d][1];
      ulonglong2 v1; v1.x = hacc[d][2]; v1.y = hacc[d][3];
      *reinterpret_cast<ulonglong2*>(r)     = v0;
      *reinterpret_cast<ulonglong2*>(r + 4) = v1;
    }
  }
}

// ---------------- kernel2 (R10, FROZEN): out[pix, o] = h[pix, :] @ w_out + b_out
// M=8192, N=256, K=512.  Block tile 128M x 64N, grid (64, 4), 256 threads.
__global__ __launch_bounds__(256) void out_gemm(const float* __restrict__ w_out,
                                                const float* __restrict__ b_out,
                                                float* __restrict__ out)
{
  __shared__ float a_sm[32*128];   // [kk][m]
  __shared__ float b_sm[32*64];    // [kk][n]
  const int t = threadIdx.x;
  const int Mbase = blockIdx.x * 128;
  const int Nbase = blockIdx.y * 64;
  const int mg = t & 15, ng = t >> 4;

  unsigned long long acc[4][4];
  #pragma unroll
  for (int j=0;j<4;j++){
    #pragma unroll
    for (int nn=0;nn<4;nn++) acc[j][nn]=0ull;
  }

  float4 ra[4], rb[2];
  #pragma unroll
  for (int i=0;i<4;i++){
    int l = i*256 + t, kk = l >> 5, mf = l & 31;
    ra[i] = __ldg(reinterpret_cast<const float4*>(g_h + (size_t)kk*8192 + Mbase + mf*4));
  }
  #pragma unroll
  for (int i=0;i<2;i++){
    int l = i*256 + t, kk = l >> 4, nf = l & 15;
    rb[i] = __ldg(reinterpret_cast<const float4*>(w_out + (size_t)kk*256 + Nbase + nf*4));
  }

  for (int kc=0; kc<16; kc++){
    #pragma unroll
    for (int i=0;i<4;i++){
      int l = i*256 + t, kk = l >> 5, mf = l & 31;
      *reinterpret_cast<float4*>(a_sm + kk*128 + mf*4) = ra[i];
    }
    #pragma unroll
    for (int i=0;i<2;i++){
      int l = i*256 + t, kk = l >> 4, nf = l & 15;
      *reinterpret_cast<float4*>(b_sm + kk*64 + nf*4) = rb[i];
    }
    __syncthreads();
    if (kc < 15){
      int k0 = (kc+1)*32;
      #pragma unroll
      for (int i=0;i<4;i++){
        int l = i*256 + t, kk = l >> 5, mf = l & 31;
        ra[i] = __ldg(reinterpret_cast<const float4*>(g_h + (size_t)(k0+kk)*8192 + Mbase + mf*4));
      }
      #pragma unroll
      for (int i=0;i<2;i++){
        int l = i*256 + t, kk = l >> 4, nf = l & 15;
        rb[i] = __ldg(reinterpret_cast<const float4*>(w_out + (size_t)(k0+kk)*256 + Nbase + nf*4));
      }
    }
    #pragma unroll 4
    for (int kk=0; kk<32; kk++){
      unsigned long long am[4];
      #pragma unroll
      for (int j=0;j<4;j++)
        am[j] = *reinterpret_cast<const unsigned long long*>(a_sm + kk*128 + 2*mg + 32*j);
      #pragma unroll
      for (int nn=0;nn<4;nn++){
        float bv = b_sm[kk*64 + ng*4 + nn];
        unsigned long long bd = pk2(bv,bv);
        #pragma unroll
        for (int j=0;j<4;j++) acc[j][nn] = f2fma(am[j], bd, acc[j][nn]);
      }
    }
    __syncthreads();
  }

  const int bb = Mbase >> 10;
  const int pl = (Mbase & 1023) + 2*mg;
  #pragma unroll
  for (int nn=0;nn<4;nn++){
    int o = Nbase + ng*4 + nn;
    float bo = __ldg(b_out + o);
    float* op = out + (size_t)bb*262144 + (size_t)o*1024 + pl;
    #pragma unroll
    for (int j=0;j<4;j++){
      float lo,hi; upk2(acc[j][nn],lo,hi);
      float2 v = make_float2(lo+bo, hi+bo);
      *reinterpret_cast<float2*>(op + 32*j) = v;
    }
  }
}

extern "C" void kernel_launch(void* const* d_in, const int* in_sizes, int n_in,
                              void* d_out, int out_size) {
  const int*   q     = (const int*)  d_in[0];
  const float* c     = (const float*)d_in[1];
  const float* rms_w = (const float*)d_in[2];
  const float* emb   = (const float*)d_in[3];
  const float* w1    = (const float*)d_in[4];
  const float* b1    = (const float*)d_in[5];
  const float* w2    = (const float*)d_in[6];
  const float* b2    = (const float*)d_in[7];
  const float* w_kv  = (const float*)d_in[8];
  const float* w_out = (const float*)d_in[9];
  const float* b_out = (const float*)d_in[10];
  float* out = (float*)d_out;

  setup_s1<<<dim3(BB, 8), 256>>>(q, emb, w1, b1);
  setup_qh<<<dim3(BB, 8), 256>>>(w2, b2);
  setup_u <<<dim3(BB, NH), 256>>>(w_kv, rms_w);

  int smem_bytes = 18944 * 4;  // 75.8KB -> 2 blocks/SM
  cudaFuncSetAttribute(main_kernel, cudaFuncAttributeMaxDynamicSharedMemorySize, smem_bytes);
  main_kernel<<<256, 256, smem_bytes>>>(c, rms_w, w_kv);

  out_gemm<<<dim3(64, 4), 256>>>(w_out, b_out, out);
}